// round 1
// baseline (speedup 1.0000x reference)
#include <cuda_runtime.h>
#include <math.h>

// ---------------------------------------------------------------------------
// CoPE: pos_vecs = normalize(pos_emb); logits = q @ pos_vecs^T / sqrt(D);
//       gates = softmax(logits, axis=-1); out = gates @ pos_vecs
// B=4, T=4096, D=4096, N=16  -> 16384 rows of length 4096, 16 codes.
// ---------------------------------------------------------------------------

#define DIM        4096
#define NPOS       16
#define ROWS_TOT   16384           // B*T
#define ROWS_BLK   16              // rows per CTA
#define NBLOCKS    (ROWS_TOT / ROWS_BLK)   // 1024
#define NTHREADS   256
#define CHUNK_F    1024            // floats of D per chunk per n-row
#define CHUNK_F4   (CHUNK_F / 4)   // 256 float4
#define NCHUNKS    (DIM / CHUNK_F) // 4

// reduction scratch layout: 4 rgrp * 64 dlane * 68 floats (stride 68 kills
// the 32-way bank conflict of stride 64; 68 keeps float offsets 4-aligned)
#define RED_STRIDE   68
#define RED_RGRP_SZ  (64 * RED_STRIDE)        // 4352 floats
#define RED_TOTAL    (4 * RED_RGRP_SZ)        // 17408 floats
#define SMEM_FLOATS  (RED_TOTAL + 256 + 256)  // + gates[16][16] + lg[16][16]
#define SMEM_BYTES   (SMEM_FLOATS * 4)        // 71680 B

__device__ float g_posn[NPOS * DIM];   // normalized codebook (scratch, no alloc)

// ---------------------------------------------------------------------------
__global__ void cope_normalize_kernel(const float* __restrict__ pos)
{
    const int n   = blockIdx.x;
    const int tid = threadIdx.x;
    const float* row = pos + n * DIM;

    float s = 0.f;
    #pragma unroll 4
    for (int i = tid; i < DIM; i += NTHREADS) {
        float v = row[i];
        s = fmaf(v, v, s);
    }
    #pragma unroll
    for (int o = 16; o > 0; o >>= 1) s += __shfl_down_sync(0xffffffffu, s, o);

    __shared__ float sred[8];
    __shared__ float sinv;
    if ((tid & 31) == 0) sred[tid >> 5] = s;
    __syncthreads();
    if (tid == 0) {
        float t = 0.f;
        #pragma unroll
        for (int w = 0; w < 8; w++) t += sred[w];
        float nrm = fmaxf(sqrtf(t), 1e-12f);
        sinv = 1.0f / nrm;
    }
    __syncthreads();
    const float inv = sinv;
    #pragma unroll 4
    for (int i = tid; i < DIM; i += NTHREADS)
        g_posn[n * DIM + i] = row[i] * inv;
}

// ---------------------------------------------------------------------------
// Fused: logits (pass 1), softmax, out (pass 2). One CTA = 16 rows.
// Thread tile: 4 rows (rgrp = tid>>6) x 16 n x 4 d (dlane = tid&63, j-loop).
// pos chunk [16][1024] fp32 staged in smem -> 4 MAC per smem float loaded,
// so the kernel is FFMA-pipe-bound, not smem-crossbar-bound.
// ---------------------------------------------------------------------------
__global__ void __launch_bounds__(NTHREADS, 2)
cope_main_kernel(const float* __restrict__ q, float* __restrict__ out)
{
    extern __shared__ float smem[];
    float*  s_buf   = smem;                 // staging (16384 f) / reduction (17408 f)
    float4* s_pos4  = (float4*)smem;        // [16][256] float4 view of pos chunk
    float*  s_gates = smem + RED_TOTAL;     // [16][16]
    float*  s_lg    = s_gates + 256;        // [16][16]

    const int tid   = threadIdx.x;
    const int rgrp  = tid >> 6;             // 0..3  (4 rows each)
    const int dlane = tid & 63;             // 0..63 (d-slice)
    const int row0  = blockIdx.x * ROWS_BLK + rgrp * 4;

    const float4* q4   = (const float4*)q;
    const float4* gp4  = (const float4*)g_posn;   // [16][1024] float4
    float4*       out4 = (float4*)out;

    // ------------------------- pass 1: logits ----------------------------
    float acc[4][16];
    #pragma unroll
    for (int r = 0; r < 4; r++)
        #pragma unroll
        for (int n = 0; n < NPOS; n++) acc[r][n] = 0.f;

    for (int c = 0; c < NCHUNKS; c++) {
        // stage pos chunk: 4096 float4, 16 per thread, fully coalesced
        #pragma unroll
        for (int i = 0; i < 16; i++) {
            int idx = tid + i * NTHREADS;          // 0..4095
            int n   = idx >> 8;                    // /256
            int d4  = idx & 255;
            s_pos4[n * CHUNK_F4 + d4] = gp4[n * (DIM / 4) + c * CHUNK_F4 + d4];
        }
        __syncthreads();

        #pragma unroll
        for (int j = 0; j < 4; j++) {
            const int d4 = dlane + j * 64;         // 0..255 in chunk
            float4 qv[4];
            #pragma unroll
            for (int r = 0; r < 4; r++)
                qv[r] = q4[(size_t)(row0 + r) * (DIM / 4) + c * CHUNK_F4 + d4];

            #pragma unroll
            for (int n = 0; n < NPOS; n++) {
                const float4 p = s_pos4[n * CHUNK_F4 + d4];
                #pragma unroll
                for (int r = 0; r < 4; r++) {
                    float a = acc[r][n];
                    a = fmaf(qv[r].x, p.x, a);
                    a = fmaf(qv[r].y, p.y, a);
                    a = fmaf(qv[r].z, p.z, a);
                    a = fmaf(qv[r].w, p.w, a);
                    acc[r][n] = a;
                }
            }
        }
        __syncthreads();
    }

    // ---------------- reduce 64 d-lanes -> logits[16][16] ----------------
    {
        float* base = s_buf + rgrp * RED_RGRP_SZ + dlane * RED_STRIDE;
        #pragma unroll
        for (int r = 0; r < 4; r++)
            #pragma unroll
            for (int n = 0; n < NPOS; n++)
                base[r * 16 + n] = acc[r][n];
    }
    __syncthreads();
    {
        const int r  = tid >> 4;                   // 0..15
        const int n  = tid & 15;
        const int rg = r >> 2, rr = r & 3;
        const float* p = s_buf + rg * RED_RGRP_SZ + rr * 16 + n;
        float s = 0.f;
        #pragma unroll 8
        for (int k = 0; k < 64; k++) s += p[k * RED_STRIDE];
        s_lg[r * 16 + n] = s * 0.015625f;          // * 1/sqrt(4096)
    }
    __syncthreads();

    // ------------------------------ softmax ------------------------------
    if (tid < ROWS_BLK) {
        const int r = tid;
        float m = -1e30f;
        #pragma unroll
        for (int n = 0; n < NPOS; n++) m = fmaxf(m, s_lg[r * 16 + n]);
        float e[NPOS];
        float sum = 0.f;
        #pragma unroll
        for (int n = 0; n < NPOS; n++) {
            e[n] = expf(s_lg[r * 16 + n] - m);
            sum += e[n];
        }
        const float inv = 1.0f / sum;
        #pragma unroll
        for (int n = 0; n < NPOS; n++) s_gates[r * 16 + n] = e[n] * inv;
    }
    __syncthreads();

    // -------------------------- pass 2: output ---------------------------
    float gt[4][16];
    #pragma unroll
    for (int r = 0; r < 4; r++)
        #pragma unroll
        for (int n = 0; n < NPOS; n++)
            gt[r][n] = s_gates[(rgrp * 4 + r) * 16 + n];

    for (int c = 0; c < NCHUNKS; c++) {
        #pragma unroll
        for (int i = 0; i < 16; i++) {
            int idx = tid + i * NTHREADS;
            int n   = idx >> 8;
            int d4  = idx & 255;
            s_pos4[n * CHUNK_F4 + d4] = gp4[n * (DIM / 4) + c * CHUNK_F4 + d4];
        }
        __syncthreads();

        #pragma unroll
        for (int j = 0; j < 4; j++) {
            const int d4 = dlane + j * 64;
            float4 o[4];
            #pragma unroll
            for (int r = 0; r < 4; r++) o[r] = make_float4(0.f, 0.f, 0.f, 0.f);

            #pragma unroll
            for (int n = 0; n < NPOS; n++) {
                const float4 p = s_pos4[n * CHUNK_F4 + d4];
                #pragma unroll
                for (int r = 0; r < 4; r++) {
                    o[r].x = fmaf(gt[r][n], p.x, o[r].x);
                    o[r].y = fmaf(gt[r][n], p.y, o[r].y);
                    o[r].z = fmaf(gt[r][n], p.z, o[r].z);
                    o[r].w = fmaf(gt[r][n], p.w, o[r].w);
                }
            }
            #pragma unroll
            for (int r = 0; r < 4; r++)
                out4[(size_t)(row0 + r) * (DIM / 4) + c * CHUNK_F4 + d4] = o[r];
        }
        __syncthreads();
    }
}

// ---------------------------------------------------------------------------
extern "C" void kernel_launch(void* const* d_in, const int* in_sizes, int n_in,
                              void* d_out, int out_size)
{
    const float* q   = (const float*)d_in[0];
    // d_in[1] = x : unused by the reference computation
    const float* pos = (const float*)d_in[2];
    float* out = (float*)d_out;

    cudaFuncSetAttribute(cope_main_kernel,
                         cudaFuncAttributeMaxDynamicSharedMemorySize, SMEM_BYTES);

    cope_normalize_kernel<<<NPOS, NTHREADS>>>(pos);
    cope_main_kernel<<<NBLOCKS, NTHREADS, SMEM_BYTES>>>(q, out);
}